// round 2
// baseline (speedup 1.0000x reference)
#include <cuda_runtime.h>
#include <cstdint>

// Scratch for per-(batch,channel) generated 3x3 kernels: 16*64*9 floats.
__device__ float g_kern[16 * 576];

// ---------------------------------------------------------------------------
// Kernel A: kernel-generating MLP.
//   hid[b][j] = lrelu(sum_i d[b][i] * Wk1[j][i])         (64,64)
//   kern[b][m] = sum_j hid[b][j] * Wk2[m][j]             m in [0,576)
// Grid: 16 blocks (one per batch), 64 threads.
// ---------------------------------------------------------------------------
__global__ void gen_kern_kernel(const float* __restrict__ d,
                                const float* __restrict__ Wk1,
                                const float* __restrict__ Wk2) {
    const int b = blockIdx.x;
    const int t = threadIdx.x;  // 0..63
    __shared__ float ds[64];
    __shared__ float hid[64];

    ds[t] = d[b * 64 + t];
    __syncthreads();

    float s = 0.f;
#pragma unroll 16
    for (int i = 0; i < 64; i++) s += ds[i] * Wk1[t * 64 + i];
    hid[t] = (s >= 0.f) ? s : 0.1f * s;
    __syncthreads();

    for (int m = t; m < 576; m += 64) {
        float a = 0.f;
        const float* w = Wk2 + (size_t)m * 64;
#pragma unroll 16
        for (int j = 0; j < 64; j++) a += hid[j] * w[j];
        g_kern[b * 576 + m] = a;
    }
}

// ---------------------------------------------------------------------------
// Kernel B: fused dynamic depthwise 3x3 (SAME, zero-pad) + LeakyReLU(0.1)
//           + 1x1 pointwise conv with bias.
// Grid: (8, 8, 16)  blocks of 256 threads; each block = one 16x16 spatial tile
// of one batch, across all 64 channels.
// Dynamic smem layout (floats):
//   xs   [64][324]  : halo tile 18x18 per channel       (82944 B)
//   wct  [64][64]   : Wc transposed, wct[c][o]          (16384 B)
//   kk   [64][12]   : 3x3 kernels, padded to 12/row     ( 3072 B)
//   bcs  [64]       : bias                              (  256 B)
// total 102656 B -> 2 blocks/SM.
// ---------------------------------------------------------------------------
#define SMEM_FLOATS (64 * 324 + 64 * 64 + 64 * 12 + 64)

__global__ __launch_bounds__(256, 2)
void da_conv_kernel(const float* __restrict__ x,
                    const float* __restrict__ Wc,
                    const float* __restrict__ bc,
                    float* __restrict__ out) {
    extern __shared__ float sm[];
    float* xs  = sm;                    // 64*324
    float* wct = xs + 64 * 324;         // 64*64
    float* kk  = wct + 64 * 64;         // 64*12
    float* bcs = kk + 64 * 12;          // 64

    const int b  = blockIdx.z;
    const int bx = blockIdx.x;
    const int by = blockIdx.y;
    const int t  = threadIdx.x;

    // Wc (o,c) -> wct[c][o]
    for (int i = t; i < 4096; i += 256) {
        int o = i >> 6, c = i & 63;
        wct[c * 64 + o] = Wc[i];
    }
    // generated kernels for this batch, padded rows of 12
    for (int i = t; i < 576; i += 256) {
        int c = i / 9, j = i - c * 9;
        kk[c * 12 + j] = g_kern[b * 576 + i];
    }
    if (t < 64) bcs[t] = bc[t];

    // halo tile load (zero padding outside)
    const int h0 = by * 16 - 1;
    const int w0 = bx * 16 - 1;
    const float* xb = x + (size_t)b * 64 * 16384;
    for (int i = t; i < 64 * 324; i += 256) {
        int c = i / 324;
        int r = (i - c * 324) / 18;
        int col = i - c * 324 - r * 18;
        int gh = h0 + r, gw = w0 + col;
        float v = 0.f;
        if ((unsigned)gh < 128u && (unsigned)gw < 128u)
            v = xb[c * 16384 + gh * 128 + gw];
        xs[i] = v;
    }
    __syncthreads();

    const int ty = t >> 4, tx = t & 15;

    float acc[64];
#pragma unroll
    for (int o = 0; o < 64; o++) acc[o] = bcs[o];

    // Rolled channel loop: dw-conv + lrelu just-in-time, rank-1 update of acc.
    for (int c = 0; c < 64; c++) {
        const float* xc = xs + c * 324 + ty * 18 + tx;
        float4 k0 = *reinterpret_cast<const float4*>(kk + c * 12);
        float4 k1 = *reinterpret_cast<const float4*>(kk + c * 12 + 4);
        float  k8 = kk[c * 12 + 8];

        float dw = xc[0]  * k0.x + xc[1]  * k0.y + xc[2]  * k0.z
                 + xc[18] * k0.w + xc[19] * k1.x + xc[20] * k1.y
                 + xc[36] * k1.z + xc[37] * k1.w + xc[38] * k8;
        float v = (dw >= 0.f) ? dw : 0.1f * dw;

        const float4* wrow = reinterpret_cast<const float4*>(wct + c * 64);
#pragma unroll
        for (int o4 = 0; o4 < 16; o4++) {
            float4 w = wrow[o4];  // broadcast LDS.128 (all lanes same addr)
            acc[4 * o4 + 0] += v * w.x;
            acc[4 * o4 + 1] += v * w.y;
            acc[4 * o4 + 2] += v * w.z;
            acc[4 * o4 + 3] += v * w.w;
        }
    }

    const int gh = by * 16 + ty;
    const int gw = bx * 16 + tx;
    float* ob = out + (size_t)b * 64 * 16384 + gh * 128 + gw;
#pragma unroll
    for (int o = 0; o < 64; o++) ob[o * 16384] = acc[o];
}

// ---------------------------------------------------------------------------
// Launch: inputs in order x, d, Wk1, Wk2, Wc, bc. Output float32 (16,64,128,128).
// ---------------------------------------------------------------------------
extern "C" void kernel_launch(void* const* d_in, const int* in_sizes, int n_in,
                              void* d_out, int out_size) {
    const float* x   = (const float*)d_in[0];
    const float* d   = (const float*)d_in[1];
    const float* Wk1 = (const float*)d_in[2];
    const float* Wk2 = (const float*)d_in[3];
    const float* Wc  = (const float*)d_in[4];
    const float* bc  = (const float*)d_in[5];
    float* out = (float*)d_out;

    gen_kern_kernel<<<16, 64>>>(d, Wk1, Wk2);

    static_assert(SMEM_FLOATS * 4 == 102656, "smem layout");
    cudaFuncSetAttribute(da_conv_kernel,
                         cudaFuncAttributeMaxDynamicSharedMemorySize,
                         SMEM_FLOATS * 4);
    dim3 grid(8, 8, 16);
    da_conv_kernel<<<grid, 256, SMEM_FLOATS * 4>>>(x, Wc, bc, out);
}